// round 13
// baseline (speedup 1.0000x reference)
#include <cuda_runtime.h>
#include <cstdint>

// 2-bit quantized embedding lookup — 256-bit stores (STG.E.256, Blackwell).
// ids: [262144] (int32 OR int64, runtime-detected in-warp), bit_arr: [3.2M]
// int32, codebook: [4] float. Token's 128 codes = 8 aligned int32 words at
// bit_arr[tok*8].
//
// One warp per 8-token group, processed as 4 token-PAIRS. Per pair:
//   lanes 0-15 -> token 2p, lanes 16-31 -> token 2p+1; m = lane&15.
//   Lane owns dims 8m..8m+7 (32B of output). One st.global.v8.f32 per pair
//   covers 1024B = 8 full 128B lines; store instruction count is halved vs
//   STG.128 (issue-cost relief on the L1/LSU path, wavefronts unchanged).
//   Gather: lane reads word m>>1 of its token (2x 32B sectors per LDG, MLP=4
//   pair-loads + id load in flight).

#define TPW 8   // tokens per warp (4 pairs)

__device__ __forceinline__ float sel2(unsigned code,
                                      float c0, float c1, float c2, float c3)
{
    float a = (code & 1u) ? c1 : c0;
    float d = (code & 1u) ? c3 : c2;
    return (code & 2u) ? d : a;
}

__device__ __forceinline__ float4 decode16(unsigned b,
                                           float c0, float c1, float c2, float c3)
{
    float4 v;
    v.x = sel2(b & 3u,        c0, c1, c2, c3);
    v.y = sel2((b >> 2) & 3u, c0, c1, c2, c3);
    v.z = sel2((b >> 4) & 3u, c0, c1, c2, c3);
    v.w = sel2((b >> 6) & 3u, c0, c1, c2, c3);
    return v;
}

__global__ void __launch_bounds__(256) embed2b_kernel(
    const unsigned* __restrict__ idw,   // ids viewed as 32-bit words
    const unsigned* __restrict__ bits,
    const float*    __restrict__ cb,
    float*          __restrict__ out,
    int n_tokens)
{
    int gt    = blockIdx.x * blockDim.x + threadIdx.x;
    int lane  = threadIdx.x & 31;
    int wbase = (gt >> 5) * TPW;        // first token of this warp

    // ---- in-warp id-dtype detection (2 cache lines, broadcast hits) ----
    // int64 ids (nonneg < 2^31): odd 32-bit words 1..63 all zero.
    // int32 ids: 32 random ids all zero w.p. ~(2.5e-6)^32 ~ 0. Deterministic.
    unsigned oddw = __ldg(idw + 2 * lane + 1);
    int stride = __any_sync(0xffffffffu, oddw != 0u) ? 1 : 2;

    if (wbase >= n_tokens) return;

    float c0 = __ldg(cb + 0);
    float c1 = __ldg(cb + 1);
    float c2 = __ldg(cb + 2);
    float c3 = __ldg(cb + 3);

    if (wbase + TPW <= n_tokens) {
        // ---- fast path: 4 token-pairs ----
        // lane l holds id of token wbase + (l&7); low word = full value (LE)
        unsigned myid = __ldg(idw + (size_t)(wbase + (lane & (TPW - 1))) * stride);

        int m    = lane & 15;           // position within the pair's 16 lanes
        int wsel = m >> 1;              // packed word this lane needs
        int hsh  = (m & 1) * 16;        // halfword shift (8 codes = 16 bits)
        bool hi  = lane >= 16;          // lanes 16-31 take the odd token

        unsigned w[TPW / 2];
        #pragma unroll
        for (int p = 0; p < TPW / 2; p++) {   // 4 independent pair-gathers
            unsigned tokA = __shfl_sync(0xffffffffu, myid, 2 * p + 0, TPW);
            unsigned tokB = __shfl_sync(0xffffffffu, myid, 2 * p + 1, TPW);
            unsigned tok  = hi ? tokB : tokA;
            w[p] = __ldg(bits + tok * 8u + wsel);   // 2x 32B sectors per LDG
        }

        #pragma unroll
        for (int p = 0; p < TPW / 2; p++) {
            unsigned b16 = w[p] >> hsh;           // 8 codes for dims 8m..8m+7
            float r0 = sel2(b16 & 3u,         c0, c1, c2, c3);
            float r1 = sel2((b16 >>  2) & 3u, c0, c1, c2, c3);
            float r2 = sel2((b16 >>  4) & 3u, c0, c1, c2, c3);
            float r3 = sel2((b16 >>  6) & 3u, c0, c1, c2, c3);
            float r4 = sel2((b16 >>  8) & 3u, c0, c1, c2, c3);
            float r5 = sel2((b16 >> 10) & 3u, c0, c1, c2, c3);
            float r6 = sel2((b16 >> 12) & 3u, c0, c1, c2, c3);
            float r7 = sel2((b16 >> 14) & 3u, c0, c1, c2, c3);

            // pair base: tokens (wbase+2p, wbase+2p+1) = 1024B contiguous.
            // lane*32B lands lanes 0-15 in token A, 16-31 in token B. 32B aligned.
            float* dst = out + (size_t)(wbase + 2 * p) * 128 + (size_t)lane * 8;
            asm volatile(
                "st.global.v8.f32 [%0], {%1, %2, %3, %4, %5, %6, %7, %8};"
                :: "l"(dst),
                   "f"(r0), "f"(r1), "f"(r2), "f"(r3),
                   "f"(r4), "f"(r5), "f"(r6), "f"(r7)
                : "memory");
        }
    } else {
        // ---- tail: per-token STG.128 (proven path) ----
        int wsel = lane >> 2;
        int bsh  = (lane & 3) * 8;
        for (int t = 0; t < TPW && wbase + t < n_tokens; t++) {
            unsigned tok = __ldg(idw + (size_t)(wbase + t) * stride);
            unsigned wv  = __ldg(bits + tok * 8u + wsel);
            float4 v = decode16(wv >> bsh, c0, c1, c2, c3);
            ((float4*)out)[(size_t)(wbase + t) * 32 + lane] = v;
        }
    }
}

extern "C" void kernel_launch(void* const* d_in, const int* in_sizes, int n_in,
                              void* d_out, int out_size)
{
    const unsigned* idw  = (const unsigned*)d_in[0];  // ids (int32 or int64)
    const unsigned* bits = (const unsigned*)d_in[1];  // packed 2-bit codes
    const float*    cb   = (const float*)d_in[2];     // 4-entry codebook
    float*          out  = (float*)d_out;             // [N, 128] fp32

    int n_tokens = in_sizes[0];                        // 64*4096 = 262144

    int warps  = (n_tokens + TPW - 1) / TPW;
    long long total_threads = (long long)warps * 32;
    int block = 256;
    int grid = (int)((total_threads + block - 1) / block);
    embed2b_kernel<<<grid, block>>>(idw, bits, cb, out, n_tokens);
}

// round 14
// speedup vs baseline: 1.1779x; 1.1779x over previous
#include <cuda_runtime.h>
#include <cstdint>

// 2-bit quantized embedding lookup — FINAL consolidated configuration (R12).
// Session evidence: warp-coalesced STG.128 stores (-15us vs dim-strided),
// MLP=8 token-group gathers (-10us); MLP=16, persistent grid, STG.256, and
// __stcs-only variants all measured neutral or worse. Four structurally
// different kernels pin at ~24-25us main-kernel time with all pipes <60%:
// the kernel sits at the L2/DRAM write-path equilibrium floor (~6 TB/s of
// L2-side traffic on the 134MB output stream).
//
// ids: [262144] (int32 OR int64, runtime-detected in-warp), bit_arr: [3.2M]
// int32, codebook: [4] float. Token's 128 codes = 8 aligned int32 words at
// bit_arr[tok*8].
//
// One warp per 8-token group: lane l loads id[base+(l&7)] (one 32B segment),
// shfl(width=8) broadcasts; 8 independent 32B-sector gathers (MLP=8); decode
// branch-free (2-level select); 8 coalesced 512B STG.128.CS bursts (4 full
// 128B lines each; evict-first keeps the 12.8MB bit_arr L2-resident).
// Lane l owns dims 4l..4l+3 of each token.

#define TPW 8   // tokens per warp

__device__ __forceinline__ float4 decode16(unsigned b,
                                           float c0, float c1, float c2, float c3)
{
    float4 v;
    {
        unsigned code = b & 3u;
        float a = (code & 1u) ? c1 : c0;
        float d = (code & 1u) ? c3 : c2;
        v.x = (code & 2u) ? d : a;
    }
    {
        unsigned code = (b >> 2) & 3u;
        float a = (code & 1u) ? c1 : c0;
        float d = (code & 1u) ? c3 : c2;
        v.y = (code & 2u) ? d : a;
    }
    {
        unsigned code = (b >> 4) & 3u;
        float a = (code & 1u) ? c1 : c0;
        float d = (code & 1u) ? c3 : c2;
        v.z = (code & 2u) ? d : a;
    }
    {
        unsigned code = (b >> 6) & 3u;
        float a = (code & 1u) ? c1 : c0;
        float d = (code & 1u) ? c3 : c2;
        v.w = (code & 2u) ? d : a;
    }
    return v;
}

__global__ void __launch_bounds__(256) embed2b_kernel(
    const unsigned* __restrict__ idw,   // ids viewed as 32-bit words
    const unsigned* __restrict__ bits,
    const float*    __restrict__ cb,
    float4*         __restrict__ out,
    int n_tokens)
{
    int gt    = blockIdx.x * blockDim.x + threadIdx.x;
    int lane  = threadIdx.x & 31;
    int wbase = (gt >> 5) * TPW;        // first token of this warp

    // ---- in-warp id-dtype detection (2 cache lines, broadcast hits) ----
    // int64 ids (nonneg < 2^31): odd 32-bit words 1..63 all zero.
    // int32 ids: 32 random ids all zero w.p. ~(2.5e-6)^32 ~ 0. Deterministic.
    unsigned oddw = __ldg(idw + 2 * lane + 1);
    int stride = __any_sync(0xffffffffu, oddw != 0u) ? 1 : 2;

    if (wbase >= n_tokens) return;

    float c0 = __ldg(cb + 0);
    float c1 = __ldg(cb + 1);
    float c2 = __ldg(cb + 2);
    float c3 = __ldg(cb + 3);

    int wsel = lane >> 2;               // which packed word this lane needs
    int bsh  = (lane & 3) * 8;          // byte shift within that word

    if (wbase + TPW <= n_tokens) {
        // ---- fast path: full group of 8 tokens ----
        // lane l holds id of token wbase + (l&7); low word = full value (LE)
        unsigned myid = __ldg(idw + (size_t)(wbase + (lane & (TPW - 1))) * stride);

        unsigned w[TPW];
        #pragma unroll
        for (int t = 0; t < TPW; t++) {         // 8 independent loads, MLP=8
            unsigned tok = __shfl_sync(0xffffffffu, myid, t, TPW);
            w[t] = __ldg(bits + tok * 8u + wsel);
        }

        #pragma unroll
        for (int t = 0; t < TPW; t++) {
            float4 v = decode16(w[t] >> bsh, c0, c1, c2, c3);
            // 4 full 128B lines per warp-store; evict-first in L2
            __stcs(out + (size_t)(wbase + t) * 32 + lane, v);
        }
    } else {
        // ---- tail: per-token ----
        for (int t = 0; t < TPW && wbase + t < n_tokens; t++) {
            unsigned tok = __ldg(idw + (size_t)(wbase + t) * stride);
            unsigned wv  = __ldg(bits + tok * 8u + wsel);
            float4 v = decode16(wv >> bsh, c0, c1, c2, c3);
            __stcs(out + (size_t)(wbase + t) * 32 + lane, v);
        }
    }
}

extern "C" void kernel_launch(void* const* d_in, const int* in_sizes, int n_in,
                              void* d_out, int out_size)
{
    const unsigned* idw  = (const unsigned*)d_in[0];  // ids (int32 or int64)
    const unsigned* bits = (const unsigned*)d_in[1];  // packed 2-bit codes
    const float*    cb   = (const float*)d_in[2];     // 4-entry codebook
    float*          out  = (float*)d_out;             // [N, 128] fp32

    int n_tokens = in_sizes[0];                        // 64*4096 = 262144

    int warps  = (n_tokens + TPW - 1) / TPW;
    long long total_threads = (long long)warps * 32;
    int block = 256;
    int grid = (int)((total_threads + block - 1) / block);
    embed2b_kernel<<<grid, block>>>(idw, bits, cb, (float4*)out, n_tokens);
}